// round 6
// baseline (speedup 1.0000x reference)
#include <cuda_runtime.h>

#define DT    0.01f
#define SIGMA 10.0f
#define RHO   28.0f
#define BETA  (8.0f / 3.0f)

__device__ __forceinline__ void lorenz(float x, float y, float z,
                                       float& dx, float& dy, float& dz) {
    dx = SIGMA * (y - x);
    dy = fmaf(x, RHO - z, -y);
    dz = fmaf(x, y, -BETA * z);
}

__device__ __forceinline__ void rk4_step(float& x, float& y, float& z) {
    float k1x, k1y, k1z, k2x, k2y, k2z, k3x, k3y, k3z, k4x, k4y, k4z;
    lorenz(x, y, z, k1x, k1y, k1z);
    lorenz(fmaf(0.5f * DT, k1x, x), fmaf(0.5f * DT, k1y, y), fmaf(0.5f * DT, k1z, z),
           k2x, k2y, k2z);
    lorenz(fmaf(0.5f * DT, k2x, x), fmaf(0.5f * DT, k2y, y), fmaf(0.5f * DT, k2z, z),
           k3x, k3y, k3z);
    lorenz(fmaf(DT, k3x, x), fmaf(DT, k3y, y), fmaf(DT, k3z, z),
           k4x, k4y, k4z);
    const float c = DT / 6.0f;
    x = fmaf(c, k1x + 2.0f * k2x + 2.0f * k3x + k4x, x);
    y = fmaf(c, k1y + 2.0f * k2y + 2.0f * k3y + k4y, y);
    z = fmaf(c, k1z + 2.0f * k2z + 2.0f * k3z + k4z, z);
}

// Each thread handles 8 states = 24 floats = 6 float4 loads/stores.
// All 6 LDG.128 are issued up-front (MLP_p1=6) with streaming hints,
// then 8 independent RK4 chains provide ILP while loads are in flight.
__global__ void __launch_bounds__(256)
lorenz_rk4_kernel(const float4* __restrict__ in, float4* __restrict__ out, int n_groups8) {
    int i = blockIdx.x * blockDim.x + threadIdx.x;
    if (i >= n_groups8) return;

    const float4* src = in  + 6 * (long long)i;
    float4*       dst = out + 6 * (long long)i;

    float4 v[6];
    #pragma unroll
    for (int j = 0; j < 6; j++)
        v[j] = __ldcs(src + j);

    // view 24 floats as 8 contiguous (x,y,z) states
    float* f = reinterpret_cast<float*>(v);
    #pragma unroll
    for (int s = 0; s < 8; s++)
        rk4_step(f[3 * s + 0], f[3 * s + 1], f[3 * s + 2]);

    #pragma unroll
    for (int j = 0; j < 6; j++)
        __stcs(dst + j, v[j]);
}

// Tail path: scalar per-state for leftover states (n % 8 != 0 case).
__global__ void lorenz_rk4_tail_kernel(const float* __restrict__ in, float* __restrict__ out,
                                       int start_state, int n_states) {
    int s = start_state + blockIdx.x * blockDim.x + threadIdx.x;
    if (s >= n_states) return;
    float x = in[3 * s + 0], y = in[3 * s + 1], z = in[3 * s + 2];
    rk4_step(x, y, z);
    out[3 * s + 0] = x;
    out[3 * s + 1] = y;
    out[3 * s + 2] = z;
}

extern "C" void kernel_launch(void* const* d_in, const int* in_sizes, int n_in,
                              void* d_out, int out_size) {
    const float* x = (const float*)d_in[0];
    float* out = (float*)d_out;

    int n_states = in_sizes[0] / 3;      // 8,000,000
    int n_groups8 = n_states / 8;        // states handled 8-at-a-time
    int tail_start = n_groups8 * 8;

    if (n_groups8 > 0) {
        int threads = 256;
        int blocks = (n_groups8 + threads - 1) / threads;
        lorenz_rk4_kernel<<<blocks, threads>>>((const float4*)x, (float4*)out, n_groups8);
    }
    if (tail_start < n_states) {
        int rem = n_states - tail_start;
        int threads = 256;
        int blocks = (rem + threads - 1) / threads;
        lorenz_rk4_tail_kernel<<<blocks, threads>>>(x, out, tail_start, n_states);
    }
}

// round 14
// speedup vs baseline: 1.1720x; 1.1720x over previous
#include <cuda_runtime.h>

#define DT    0.01f
#define SIGMA 10.0f
#define RHO   28.0f
#define BETA  (8.0f / 3.0f)

__device__ __forceinline__ void lorenz(float x, float y, float z,
                                       float& dx, float& dy, float& dz) {
    dx = SIGMA * (y - x);
    dy = fmaf(x, RHO - z, -y);
    dz = fmaf(x, y, -BETA * z);
}

__device__ __forceinline__ void rk4_step(float& x, float& y, float& z) {
    float k1x, k1y, k1z, k2x, k2y, k2z, k3x, k3y, k3z, k4x, k4y, k4z;
    lorenz(x, y, z, k1x, k1y, k1z);
    lorenz(fmaf(0.5f * DT, k1x, x), fmaf(0.5f * DT, k1y, y), fmaf(0.5f * DT, k1z, z),
           k2x, k2y, k2z);
    lorenz(fmaf(0.5f * DT, k2x, x), fmaf(0.5f * DT, k2y, y), fmaf(0.5f * DT, k2z, z),
           k3x, k3y, k3z);
    lorenz(fmaf(DT, k3x, x), fmaf(DT, k3y, y), fmaf(DT, k3z, z),
           k4x, k4y, k4z);
    const float c = DT / 6.0f;
    x = fmaf(c, k1x + 2.0f * k2x + 2.0f * k3x + k4x, x);
    y = fmaf(c, k1y + 2.0f * k2y + 2.0f * k3y + k4y, y);
    z = fmaf(c, k1z + 2.0f * k2z + 2.0f * k3z + k4z, z);
}

// Each thread handles TWO far-strided groups of 4 states (group i and i+half).
// 6 LDG.128 are issued up-front (MLP_p1=6) with PLAIN loads (no cache hints),
// named-float4 codegen like the 30.7us baseline.
__global__ void __launch_bounds__(256)
lorenz_rk4_kernel(const float4* __restrict__ in, float4* __restrict__ out, int half) {
    int i = blockIdx.x * blockDim.x + threadIdx.x;
    if (i >= half) return;

    long long g0 = 3LL * i;
    long long g1 = 3LL * (i + half);

    float4 a0 = in[g0 + 0];
    float4 a1 = in[g0 + 1];
    float4 a2 = in[g0 + 2];
    float4 b0 = in[g1 + 0];
    float4 b1 = in[g1 + 1];
    float4 b2 = in[g1 + 2];

    // group 0 states: (a0.x,a0.y,a0.z) (a0.w,a1.x,a1.y) (a1.z,a1.w,a2.x) (a2.y,a2.z,a2.w)
    rk4_step(a0.x, a0.y, a0.z);
    rk4_step(a0.w, a1.x, a1.y);
    rk4_step(a1.z, a1.w, a2.x);
    rk4_step(a2.y, a2.z, a2.w);
    // group 1 states
    rk4_step(b0.x, b0.y, b0.z);
    rk4_step(b0.w, b1.x, b1.y);
    rk4_step(b1.z, b1.w, b2.x);
    rk4_step(b2.y, b2.z, b2.w);

    out[g0 + 0] = a0;
    out[g0 + 1] = a1;
    out[g0 + 2] = a2;
    out[g1 + 0] = b0;
    out[g1 + 1] = b1;
    out[g1 + 2] = b2;
}

// Fallback: one group of 4 states per thread (used when group count is odd).
__global__ void __launch_bounds__(256)
lorenz_rk4_single_kernel(const float4* __restrict__ in, float4* __restrict__ out,
                         int start_group, int n_groups) {
    int i = start_group + blockIdx.x * blockDim.x + threadIdx.x;
    if (i >= n_groups) return;
    long long g = 3LL * i;
    float4 a0 = in[g + 0];
    float4 a1 = in[g + 1];
    float4 a2 = in[g + 2];
    rk4_step(a0.x, a0.y, a0.z);
    rk4_step(a0.w, a1.x, a1.y);
    rk4_step(a1.z, a1.w, a2.x);
    rk4_step(a2.y, a2.z, a2.w);
    out[g + 0] = a0;
    out[g + 1] = a1;
    out[g + 2] = a2;
}

// Tail path: scalar per-state for leftover states (n % 4 != 0 case).
__global__ void lorenz_rk4_tail_kernel(const float* __restrict__ in, float* __restrict__ out,
                                       int start_state, int n_states) {
    int s = start_state + blockIdx.x * blockDim.x + threadIdx.x;
    if (s >= n_states) return;
    float x = in[3 * s + 0], y = in[3 * s + 1], z = in[3 * s + 2];
    rk4_step(x, y, z);
    out[3 * s + 0] = x;
    out[3 * s + 1] = y;
    out[3 * s + 2] = z;
}

extern "C" void kernel_launch(void* const* d_in, const int* in_sizes, int n_in,
                              void* d_out, int out_size) {
    const float* x = (const float*)d_in[0];
    float* out = (float*)d_out;

    int n_states  = in_sizes[0] / 3;   // 8,000,000
    int n_groups4 = n_states / 4;      // 2,000,000 float4-triples
    int half      = n_groups4 / 2;     // 1,000,000 threads, 2 groups each
    int threads   = 256;

    if (half > 0) {
        int blocks = (half + threads - 1) / threads;
        lorenz_rk4_kernel<<<blocks, threads>>>((const float4*)x, (float4*)out, half);
    }
    if (2 * half < n_groups4) {  // odd group count
        int rem = n_groups4 - 2 * half;
        int blocks = (rem + threads - 1) / threads;
        lorenz_rk4_single_kernel<<<blocks, threads>>>((const float4*)x, (float4*)out,
                                                      2 * half, n_groups4);
    }
    int tail_start = n_groups4 * 4;
    if (tail_start < n_states) {
        int rem = n_states - tail_start;
        int blocks = (rem + threads - 1) / threads;
        lorenz_rk4_tail_kernel<<<blocks, threads>>>(x, out, tail_start, n_states);
    }
}